// round 1
// baseline (speedup 1.0000x reference)
#include <cuda_runtime.h>
#include <cuda_bf16.h>

// OverlapPatchEmbed: extract overlapping 16x16 patches with stride 8 from
// x[64, 3, 224, 224] -> out[64, 729, 3, 256] (fp32).
//
// out[b, py*27+px, c, ky*16+kx] = x[b, c, py*8+ky, px*8+kx]
//
// Pure memory-movement kernel. One thread per output float4:
//   - output stores: fully linear/coalesced
//   - input loads: aligned 16B vector loads; input (38.5 MB) fits in L2 so the
//     4x overlap replication is served from L2, not DRAM.

#define B_    64
#define C_    3
#define H_    224
#define W_    224
#define PS_   16
#define STR_  8
#define N_    27          // (224-16)/8 + 1
// total output floats = 64*729*3*256 = 35,831,808 ; float4s = 8,957,952
#define NOUT4 8957952

__global__ __launch_bounds__(256) void overlap_patch_kernel(
    const float* __restrict__ x, float4* __restrict__ out)
{
    int t = blockIdx.x * blockDim.x + threadIdx.x;
    if (t >= NOUT4) return;

    // t enumerates (b, py, px, c, ky, kx4) with kx4 in [0,4)
    int kx4 = t & 3;          // 4 float4s per 16-wide patch row
    int r   = t >> 2;
    int ky  = r & 15;         // 16 rows per patch
    r >>= 4;
    int c   = r % 3;
    r /= 3;
    int px  = r % N_;
    r /= N_;
    int py  = r % N_;
    int b   = r / N_;

    // input float index (guaranteed multiple of 4 -> aligned float4 load)
    int row  = py * STR_ + ky;
    int col  = px * STR_ + kx4 * 4;
    long in_f = (((long)(b * C_ + c) * H_) + row) * W_ + col;

    out[t] = *reinterpret_cast<const float4*>(x + in_f);
}

extern "C" void kernel_launch(void* const* d_in, const int* in_sizes, int n_in,
                              void* d_out, int out_size)
{
    const float* x = (const float*)d_in[0];
    float4* out = (float4*)d_out;
    int blocks = (NOUT4 + 255) / 256;
    overlap_patch_kernel<<<blocks, 256>>>(x, out);
}

// round 2
// speedup vs baseline: 1.2463x; 1.2463x over previous
#include <cuda_runtime.h>
#include <cuda_bf16.h>

// OverlapPatchEmbed: extract overlapping 16x16 patches with stride 8 from
// x[64, 3, 224, 224] -> out[64, 729, 3, 256] (fp32).
//
// out[b, py*27+px, c, ky*16+kx] = x[b, c, py*8+ky, px*8+kx]
//
// R2: latency-bound fix. Each thread handles ITERS=4 output float4s spaced by
// the total thread count. Addresses computed up front, 4 independent LDG.128
// issued back-to-back (MLP=4/thread), then 4 STG.128. Coalescing identical to
// R1 (every slice is a linear warp access).

#define C_    3
#define H_    224
#define W_    224
#define STR_  8
#define N_    27                  // (224-16)/8 + 1
#define NOUT4 8957952             // 64*729*3*256 / 4
#define ITERS 4
#define NTHREADS (NOUT4 / ITERS)  // 2,239,488 = 8748 * 256

__device__ __forceinline__ long in_index(int t)
{
    // t enumerates (b, py, px, c, ky, kx4) with kx4 in [0,4)
    int kx4 = t & 3;
    int r   = t >> 2;
    int ky  = r & 15;
    r >>= 4;
    int c   = r % 3;
    r /= 3;
    int px  = r % N_;
    r /= N_;
    int py  = r % N_;
    int b   = r / N_;

    int row = py * STR_ + ky;
    int col = px * STR_ + (kx4 << 2);
    return (((long)(b * C_ + c) * H_) + row) * W_ + col;  // multiple of 4
}

__global__ __launch_bounds__(256) void overlap_patch_kernel(
    const float* __restrict__ x, float4* __restrict__ out)
{
    int tid = blockIdx.x * blockDim.x + threadIdx.x;

    long a0 = in_index(tid);
    long a1 = in_index(tid + NTHREADS);
    long a2 = in_index(tid + 2 * NTHREADS);
    long a3 = in_index(tid + 3 * NTHREADS);

    float4 v0 = *reinterpret_cast<const float4*>(x + a0);
    float4 v1 = *reinterpret_cast<const float4*>(x + a1);
    float4 v2 = *reinterpret_cast<const float4*>(x + a2);
    float4 v3 = *reinterpret_cast<const float4*>(x + a3);

    out[tid]                = v0;
    out[tid + NTHREADS]     = v1;
    out[tid + 2 * NTHREADS] = v2;
    out[tid + 3 * NTHREADS] = v3;
}

extern "C" void kernel_launch(void* const* d_in, const int* in_sizes, int n_in,
                              void* d_out, int out_size)
{
    const float* x = (const float*)d_in[0];
    float4* out = (float4*)d_out;
    overlap_patch_kernel<<<NTHREADS / 256, 256>>>(x, out);
}

// round 3
// speedup vs baseline: 1.3805x; 1.1077x over previous
#include <cuda_runtime.h>
#include <cuda_bf16.h>

// OverlapPatchEmbed: x[64,3,224,224] -> out[64,729,3,256] (fp32)
// out[b, py*27+px, c, ky*16+kx] = x[b, c, py*8+ky, px*8+kx]
//
// R3: SMEM staging. Block = (py, c, b). Stage the 16 contiguous input rows
// (14336 B, one linear span) into padded SMEM, then emit the 27 overlapping
// patches with linear coalesced stores. The 4x overlap replication is served
// from SMEM instead of L1/L2.

#define C_     3
#define W_     224
#define STR_   8
#define N_     27
#define ROWS_  16
#define PADF   240                    // floats per smem row (240 mod 32 == 16)
#define PAD4   (PADF / 4)             // 60 float4 per smem row
#define W4     (W_ / 4)               // 56 float4 per input row
#define STAGE4 (ROWS_ * W4)           // 896 float4 staged per block
#define OUT4   (N_ * 64)              // 1728 float4 written per block

__global__ __launch_bounds__(256) void overlap_patch_kernel(
    const float4* __restrict__ x, float4* __restrict__ out)
{
    __shared__ float4 s[ROWS_ * PAD4];          // 15360 B

    const int py = blockIdx.x;
    const int c  = blockIdx.y;
    const int b  = blockIdx.z;
    const int tid = threadIdx.x;

    // ---- stage: 16 contiguous rows, fully linear global load ----
    // global float4 base of row (py*8) for this (b, c)
    const long gbase = ((long)(b * C_ + c) * 224 + py * STR_) * W4;
    const float4* gsrc = x + gbase;

    float4 v0 = gsrc[tid];
    float4 v1 = gsrc[tid + 256];
    float4 v2 = gsrc[tid + 512];
    float4 v3;
    if (tid < STAGE4 - 768) v3 = gsrc[tid + 768];

    {
        int i = tid;
        s[(i / W4) * PAD4 + (i % W4)] = v0;
        i = tid + 256;
        s[(i / W4) * PAD4 + (i % W4)] = v1;
        i = tid + 512;
        s[(i / W4) * PAD4 + (i % W4)] = v2;
        if (tid < STAGE4 - 768) {
            i = tid + 768;
            s[(i / W4) * PAD4 + (i % W4)] = v3;
        }
    }
    __syncthreads();

    // ---- emit: 27 patches x 64 float4, linear coalesced stores ----
    // out float4 index = ((b*729 + py*27 + px)*3 + c)*64 + ky*4 + kx4
    const long obase = (((long)b * 729 + py * N_) * C_ + c) * 64;
    float4* __restrict__ o = out + obase;

    const float* sf = reinterpret_cast<const float*>(s);

    #pragma unroll
    for (int k = 0; k < 7; k++) {
        int idx = tid + k * 256;
        if (idx < OUT4) {
            int kx4 = idx & 3;
            int ky  = (idx >> 2) & 15;
            int px  = idx >> 6;
            // smem float addr: ky*PADF + px*8 + kx4*4  (16B aligned)
            float4 v = *reinterpret_cast<const float4*>(
                sf + ky * PADF + px * STR_ + (kx4 << 2));
            o[px * (C_ * 64) + (ky << 2) + kx4] = v;
        }
    }
}

extern "C" void kernel_launch(void* const* d_in, const int* in_sizes, int n_in,
                              void* d_out, int out_size)
{
    const float4* x = (const float4*)d_in[0];
    float4* out = (float4*)d_out;
    dim3 grid(N_, C_, 64);
    overlap_patch_kernel<<<grid, 256>>>(x, out);
}

// round 4
// speedup vs baseline: 1.3819x; 1.0010x over previous
#include <cuda_runtime.h>
#include <cuda_bf16.h>

// OverlapPatchEmbed: x[64,3,224,224] -> out[64,729,3,256] (fp32)
// out[b, py*27+px, c, ky*16+kx] = x[b, c, py*8+ky, px*8+kx]
//
// R4: block = (py, b) stages ALL 3 channels (48 rows, 45KB smem) and writes a
// fully contiguous 81KB output region (out index == linear intra-block index).
// 512 threads, 4 blocks/SM = 100% occupancy. Streaming stores (__stcs) keep
// L2 for the input so DRAM reads are one-time.

#define W4      56                 // float4 per input row
#define PAD4    60                 // float4 per padded smem row
#define PADF    240                // floats per padded smem row
#define CH_S4   (16 * PAD4)        // 960 float4 per staged channel
#define STAGE4  (3 * 16 * W4)      // 2688 float4 staged per block
#define EMIT4   (27 * 3 * 64)      // 5184 float4 emitted per block
#define NT      512

__global__ __launch_bounds__(NT) void overlap_patch_kernel(
    const float4* __restrict__ x, float4* __restrict__ out)
{
    __shared__ float4 s[3 * CH_S4];            // 46080 B

    const int py  = blockIdx.x;
    const int b   = blockIdx.y;
    const int tid = threadIdx.x;

    // ---- stage: 3 channels x 16 contiguous rows, linear global loads ----
    // channel ch base (float4): ((b*3+ch)*224 + py*8) * 56
    const long g0 = ((long)(b * 3) * 224 + py * 8) * W4;
    const int  gch = 224 * W4;                 // channel stride in float4

    #pragma unroll
    for (int k = 0; k < 6; k++) {
        int idx = tid + k * NT;
        if (idx < STAGE4) {
            int ch  = idx / (16 * W4);         // 896 f4 per channel
            int r   = idx - ch * (16 * W4);
            int row = r / W4;
            int col = r - row * W4;
            float4 v = x[g0 + (long)ch * gch + r];
            s[ch * CH_S4 + row * PAD4 + col] = v;
        }
    }
    __syncthreads();

    // ---- emit: 81KB contiguous region, out index == intra-block index ----
    const long obase = ((long)b * 729 + py * 27) * (3 * 64);
    float4* __restrict__ o = out + obase;
    const float* sf = reinterpret_cast<const float*>(s);

    #pragma unroll
    for (int k = 0; k < 11; k++) {
        int idx = tid + k * NT;
        if (idx < EMIT4) {
            int kx4 = idx & 3;
            int ky  = (idx >> 2) & 15;
            int t   = idx >> 6;                // px*3 + c
            int c   = t % 3;
            int px  = t / 3;
            float4 v = *reinterpret_cast<const float4*>(
                sf + c * (CH_S4 * 4) + ky * PADF + px * 8 + (kx4 << 2));
            __stcs(o + idx, v);
        }
    }
}

extern "C" void kernel_launch(void* const* d_in, const int* in_sizes, int n_in,
                              void* d_out, int out_size)
{
    const float4* x = (const float4*)d_in[0];
    float4* out = (float4*)d_out;
    dim3 grid(27, 64);
    overlap_patch_kernel<<<grid, NT>>>(x, out);
}